// round 16
// baseline (speedup 1.0000x reference)
#include <cuda_runtime.h>
#include <cuda_fp16.h>
#include <cstdint>
#include <math.h>

// Problem dims (fixed per reference)
constexpr int B_ = 16;
constexpr int L_ = 1024;
constexpr int D_ = 1024;
#define NEGV (-1e10f)

// ======================= static device scratch ==============================
__device__ __align__(16) float  g_scores[(size_t)B_ * L_ * L_]; // fp32 scores
__device__ __align__(16) __half g_attnH[(size_t)B_ * L_ * L_];  // half attn
__device__ __align__(16) __half g_awH[(size_t)B_ * L_ * D_];    // half(inp*w3)
__device__ __align__(16) __half g_inpH[(size_t)B_ * L_ * D_];   // half(inp)
__device__ __align__(16) __half g_inpTH[(size_t)B_ * L_ * D_];  // half(inp)^T per batch
__device__ __align__(16) __half g_c2qH[(size_t)B_ * L_ * D_];   // half(c2q)
__device__ __align__(16) __half g_xcH[(size_t)B_ * L_ * D_];    // half(inp*c2q)
__device__ __align__(16) __half g_WmTH[(size_t)3 * D_ * D_];    // half(Wm)^T [D, 3D]
__device__ __align__(16) float  g_sq[B_ * L_];
__device__ int g_mask_is_byte;

// ======================= small helpers ======================================
__device__ __forceinline__ uint32_t smem_u32(const void* p) {
    uint32_t a;
    asm("{ .reg .u64 t; cvta.to.shared.u64 t, %1; cvt.u32.u64 %0, t; }" : "=r"(a) : "l"(p));
    return a;
}
__device__ __forceinline__ void cp16(uint32_t dst, const void* src) {
    asm volatile("cp.async.cg.shared.global [%0], [%1], 16;" :: "r"(dst), "l"(src));
}
__device__ __forceinline__ int mask_at(const void* mask, int idx, int is_byte) {
    if (is_byte) return ((const unsigned char*)mask)[idx] != 0;
    return ((const int*)mask)[idx] != 0;
}
__device__ __forceinline__ void mma_f16(float* d, const uint32_t* a, const uint32_t* b) {
    asm volatile(
        "mma.sync.aligned.m16n8k16.row.col.f32.f16.f16.f32 "
        "{%0,%1,%2,%3}, {%4,%5,%6,%7}, {%8,%9}, {%0,%1,%2,%3};"
        : "+f"(d[0]), "+f"(d[1]), "+f"(d[2]), "+f"(d[3])
        : "r"(a[0]), "r"(a[1]), "r"(a[2]), "r"(a[3]), "r"(b[0]), "r"(b[1]));
}
__device__ __forceinline__ void ldsm_x4(uint32_t addr, uint32_t& r0, uint32_t& r1,
                                        uint32_t& r2, uint32_t& r3) {
    asm volatile("ldmatrix.sync.aligned.m8n8.x4.shared.b16 {%0,%1,%2,%3}, [%4];"
                 : "=r"(r0), "=r"(r1), "=r"(r2), "=r"(r3) : "r"(addr));
}

// ======================= mask dtype autodetect ==============================
__global__ void k_detect(const unsigned char* __restrict__ mask) {
    __shared__ int found;
    if (threadIdx.x == 0) found = 0;
    __syncthreads();
    int any = 0;
    for (int p = threadIdx.x; p < B_ * L_; p += blockDim.x)
        if ((p & 3) && mask[p]) any = 1;
    if (any) atomicOr(&found, 1);
    __syncthreads();
    if (threadIdx.x == 0) g_mask_is_byte = found;
}

// ======================= fused prep: awH, inpH, inpTH (one read of inp) =====
__global__ void k_prep_all(const float* __restrict__ inp, const float* __restrict__ wsim) {
    __shared__ float t[32][33];
    int b  = blockIdx.z;
    int d0 = blockIdx.x * 32;
    int j0 = blockIdx.y * 32;
    const float* src = inp + (size_t)b * L_ * D_;
    float w3v = wsim[2 * D_ + d0 + threadIdx.x];
    #pragma unroll
    for (int k = 0; k < 4; k++) {
        int j = j0 + threadIdx.y + 8 * k;
        float v = src[(size_t)j * D_ + d0 + threadIdx.x];
        t[threadIdx.y + 8 * k][threadIdx.x] = v;
        size_t off = (size_t)b * L_ * D_ + (size_t)j * D_ + d0 + threadIdx.x;
        g_inpH[off] = __float2half_rn(v);
        g_awH[off]  = __float2half_rn(v * w3v);
    }
    __syncthreads();
    __half* dst = g_inpTH + (size_t)b * L_ * D_;
    #pragma unroll
    for (int k = 0; k < 4; k++)
        dst[(size_t)(d0 + threadIdx.y + 8 * k) * L_ + j0 + threadIdx.x] =
            __float2half_rn(t[threadIdx.x][threadIdx.y + 8 * k]);
}

// ======================= s_q (fp32) =========================================
// s_c (per-row constant) cancels under softmax and is dropped entirely.
__global__ void k_sq(const float* __restrict__ inp, const float* __restrict__ wsim) {
    int row = blockIdx.x * (blockDim.x >> 5) + (threadIdx.x >> 5);
    if (row >= B_ * L_) return;
    int lane = threadIdx.x & 31;
    const float* x = inp + (size_t)row * D_;
    float s2 = 0.f;
    for (int d = lane; d < D_; d += 32)
        s2 += x[d] * wsim[D_ + d];
    #pragma unroll
    for (int o = 16; o; o >>= 1)
        s2 += __shfl_xor_sync(0xffffffffu, s2, o);
    if (lane == 0) g_sq[row] = s2;
}

// ======================= transpose Wm (write half) ==========================
__global__ void k_transpose_wm(const float* __restrict__ Wm) {
    __shared__ float t[32][33];
    int n0 = blockIdx.x * 32;   // col of Wm (D)
    int k0 = blockIdx.y * 32;   // row of Wm (3D)
    #pragma unroll
    for (int k = 0; k < 4; k++)
        t[threadIdx.y + 8 * k][threadIdx.x] =
            Wm[(size_t)(k0 + threadIdx.y + 8 * k) * D_ + n0 + threadIdx.x];
    __syncthreads();
    #pragma unroll
    for (int k = 0; k < 4; k++)
        g_WmTH[(size_t)(n0 + threadIdx.y + 8 * k) * (3 * D_) + k0 + threadIdx.x] =
            __float2half_rn(t[threadIdx.x][threadIdx.y + 8 * k]);
}

// ======================= softmax: fp32 scores -> half attn ==================
__global__ void k_softmax(const void* __restrict__ mask) {
    __shared__ float redmax[8];
    __shared__ float redsum[8];
    int row = blockIdx.x;
    int b   = row >> 10;
    int isb = g_mask_is_byte;
    const float* s = g_scores + (size_t)row * L_;
    __half* a = g_attnH + (size_t)row * L_;
    int t = threadIdx.x;

    float4 v = ((const float4*)s)[t];
    int j0 = t << 2;
    int base = b * L_;
    if (mask_at(mask, base + j0 + 0, isb)) v.x = NEGV;
    if (mask_at(mask, base + j0 + 1, isb)) v.y = NEGV;
    if (mask_at(mask, base + j0 + 2, isb)) v.z = NEGV;
    if (mask_at(mask, base + j0 + 3, isb)) v.w = NEGV;

    float mx = fmaxf(fmaxf(v.x, v.y), fmaxf(v.z, v.w));
    #pragma unroll
    for (int o = 16; o; o >>= 1) mx = fmaxf(mx, __shfl_xor_sync(0xffffffffu, mx, o));
    if ((t & 31) == 0) redmax[t >> 5] = mx;
    __syncthreads();
    mx = fmaxf(fmaxf(fmaxf(redmax[0], redmax[1]), fmaxf(redmax[2], redmax[3])),
               fmaxf(fmaxf(redmax[4], redmax[5]), fmaxf(redmax[6], redmax[7])));

    v.x = __expf(v.x - mx); v.y = __expf(v.y - mx);
    v.z = __expf(v.z - mx); v.w = __expf(v.w - mx);
    float sm = v.x + v.y + v.z + v.w;
    #pragma unroll
    for (int o = 16; o; o >>= 1) sm += __shfl_xor_sync(0xffffffffu, sm, o);
    if ((t & 31) == 0) redsum[t >> 5] = sm;
    __syncthreads();
    sm = redsum[0] + redsum[1] + redsum[2] + redsum[3] +
         redsum[4] + redsum[5] + redsum[6] + redsum[7];
    float inv = 1.0f / sm;
    ((__half2*)a)[2 * t]     = __floats2half2_rn(v.x * inv, v.y * inv);
    ((__half2*)a)[2 * t + 1] = __floats2half2_rn(v.z * inv, v.w * inv);
}

// ======================= fp16 HMMA GEMM (ldmatrix, BK=64, pipelined) ========
// CTA tile M=128, N=128, BK=64 halves. 8 warps (2 M x 4 N), each 64x32 via
// m16n8k16. SMEM rows 128B data padded to 144B stride — conflict-free for
// ldmatrix (banks 4r mod 32). 3-stage cp.async pipeline, occupancy 2.
// Mainloop: next chunk's cp.async issued right after the barrier; ldmatrix
// fragments register-double-buffered (load ks+1 before MMAs of ks).
// E=1: scores(fp32) = awH @ inpH^T (+sq)        [per batch]
// E=2: c2qH/xcH     = attnH @ inpTH^T           [per batch]
// E=3: out(fp32)    = [inpH|c2qH|xcH] @ WmTH^T (+bias, relu, mask)
constexpr int ROWB = 144;                        // smem row stride (bytes)
constexpr int STAGE_BYTES = 2 * 128 * ROWB;      // 36864
constexpr int SMEM_TOTAL = 3 * STAGE_BYTES;      // 110592

template <int E>
__global__ __launch_bounds__(256, 2)
void k_gemm_mma(const float* __restrict__ bias, const void* __restrict__ mask,
                float* __restrict__ out) {
    extern __shared__ char smem[];
    uint32_t sbase = smem_u32(smem);
    int tid = threadIdx.x;
    int lane = tid & 31, w = tid >> 5;
    int g = lane >> 2, t = lane & 3;
    int wm = w & 1, wn = w >> 1;                 // warp grid 2 (M) x 4 (N)

    constexpr int NCH = (E == 3) ? 48 : 16;      // K chunks of 64 halves
    constexpr int LDB = (E == 3) ? 3072 : 1024;

    int b  = blockIdx.z;
    int i0 = blockIdx.y * 128;
    int n0 = blockIdx.x * 128;

    const __half *A0, *A1 = nullptr, *A2 = nullptr, *Bb;
    if (E == 1) {
        A0 = g_awH  + ((size_t)b << 20) + (size_t)i0 * 1024;
        Bb = g_inpH + ((size_t)b << 20) + (size_t)n0 * 1024;
    } else if (E == 2) {
        A0 = g_attnH + ((size_t)b << 20) + (size_t)i0 * 1024;
        Bb = g_inpTH + ((size_t)b << 20) + (size_t)n0 * 1024;
    } else {
        A0 = g_inpH + (size_t)i0 * 1024;
        A1 = g_c2qH + (size_t)i0 * 1024;
        A2 = g_xcH  + (size_t)i0 * 1024;
        Bb = g_WmTH + (size_t)n0 * 3072;
    }

    // ldmatrix per-lane address offsets (within a stage)
    int mat = lane >> 3, mrow = lane & 7;
    // A (x4: {rows+0,+0B},{rows+8,+0B},{rows+0,+16B},{rows+8,+16B})
    uint32_t offA = (uint32_t)(wm * 64 + (mat & 1) * 8 + mrow) * ROWB + (mat >> 1) * 16;
    // B (x4: {nt0,+0B},{nt0,+16B},{nt1,+0B},{nt1,+16B})
    uint32_t offB = (uint32_t)(wn * 32 + (mat >> 1) * 8 + mrow) * ROWB + (mat & 1) * 16;

    // load one K-chunk (64 halves = 128B/row): A 128 rows, B 128 rows
    auto loadc = [&](int kc, int s) {
        const __half* Ab;
        int koff;
        if (E == 3) {
            int seg = kc >> 4;
            koff = (kc & 15) * 64;
            Ab = (seg == 0) ? A0 : (seg == 1) ? A1 : A2;
        } else {
            Ab = A0; koff = kc * 64;
        }
        const __half* Bv = Bb + (size_t)kc * 64;
        uint32_t sa = sbase + s * STAGE_BYTES;
        uint32_t sb = sa + 128 * ROWB;
        #pragma unroll
        for (int r = 0; r < 4; r++) {
            int id = tid + r * 256;
            int row = id >> 3, c8 = id & 7;
            cp16(sa + row * ROWB + c8 * 16, Ab + (size_t)row * 1024 + koff + c8 * 8);
        }
        #pragma unroll
        for (int r = 0; r < 4; r++) {
            int id = tid + r * 256;
            int row = id >> 3, c8 = id & 7;
            cp16(sb + row * ROWB + c8 * 16, Bv + (size_t)row * LDB + c8 * 8);
        }
    };

    auto ldfragsA = [&](uint32_t As, int ks, uint32_t af[4][4]) {
        uint32_t kbyte = ks * 32;
        #pragma unroll
        for (int mt = 0; mt < 4; mt++)
            ldsm_x4(As + offA + mt * 16 * ROWB + kbyte,
                    af[mt][0], af[mt][1], af[mt][2], af[mt][3]);
    };
    auto ldfragsB = [&](uint32_t Bs, int ks, uint32_t bf[4][2]) {
        uint32_t kbyte = ks * 32;
        #pragma unroll
        for (int np = 0; np < 2; np++)
            ldsm_x4(Bs + offB + np * 16 * ROWB + kbyte,
                    bf[2 * np][0], bf[2 * np][1],
                    bf[2 * np + 1][0], bf[2 * np + 1][1]);
    };

    float acc[4][4][4];
    #pragma unroll
    for (int i = 0; i < 4; i++)
        #pragma unroll
        for (int j = 0; j < 4; j++)
            #pragma unroll
            for (int q = 0; q < 4; q++) acc[i][j][q] = 0.f;

    // prologue: stages 0..1
    #pragma unroll
    for (int c = 0; c < 2; c++) {
        loadc(c, c);
        asm volatile("cp.async.commit_group;" ::: "memory");
    }

    uint32_t af[2][4][4], bf[2][4][2];
    int stage = 0;
    for (int kc = 0; kc < NCH; kc++) {
        asm volatile("cp.async.wait_group 1;" ::: "memory");
        __syncthreads();

        uint32_t As = sbase + stage * STAGE_BYTES;
        uint32_t Bs = As + 128 * ROWB;

        // first fragment set for this chunk
        ldfragsA(As, 0, af[0]);
        ldfragsB(Bs, 0, bf[0]);

        // issue next chunk's global->smem copies early (stage was last read
        // in iteration kc-1; barrier above makes the overwrite safe)
        int lc = kc + 2;
        if (lc < NCH) {
            int ls = stage + 2; if (ls >= 3) ls -= 3;
            loadc(lc, ls);
        }
        asm volatile("cp.async.commit_group;" ::: "memory");

        #pragma unroll
        for (int ks = 0; ks < 4; ks++) {
            int cur = ks & 1;
            if (ks < 3) {
                ldfragsA(As, ks + 1, af[cur ^ 1]);
                ldfragsB(Bs, ks + 1, bf[cur ^ 1]);
            }
            #pragma unroll
            for (int mt = 0; mt < 4; mt++)
                #pragma unroll
                for (int nt = 0; nt < 4; nt++)
                    mma_f16(acc[mt][nt], af[cur][mt], bf[cur][nt]);
        }

        if (++stage == 3) stage = 0;
    }

    // ---------------- epilogue ------------------------------------------------
    int isb = (E == 3) ? g_mask_is_byte : 0;
    #pragma unroll
    for (int mt = 0; mt < 4; mt++) {
        int grow0 = i0 + wm * 64 + mt * 16 + g;      // rows grow0, grow0+8
        if (E == 1) {
            float* c0 = g_scores + ((size_t)b << 20) + (size_t)grow0 * 1024;
            #pragma unroll
            for (int nt = 0; nt < 4; nt++) {
                int gcol = n0 + wn * 32 + nt * 8 + 2 * t;
                float2 sq2 = *(const float2*)(g_sq + b * 1024 + gcol);
                float2 o0 = make_float2(acc[mt][nt][0] + sq2.x,
                                        acc[mt][nt][1] + sq2.y);
                float2 o1 = make_float2(acc[mt][nt][2] + sq2.x,
                                        acc[mt][nt][3] + sq2.y);
                *(float2*)(c0 + gcol) = o0;
                *(float2*)(c0 + 8 * 1024 + gcol) = o1;
            }
        } else if (E == 2) {
            size_t base0 = ((size_t)(b * 1024 + grow0)) * 1024;
            #pragma unroll
            for (int nt = 0; nt < 4; nt++) {
                int gcol = n0 + wn * 32 + nt * 8 + 2 * t;
                float2 x0 = __half22float2(*(const __half2*)(g_inpH + base0 + gcol));
                float2 x1 = __half22float2(*(const __half2*)(g_inpH + base0 + 8 * 1024 + gcol));
                __half2 c0h = __floats2half2_rn(acc[mt][nt][0], acc[mt][nt][1]);
                __half2 c1h = __floats2half2_rn(acc[mt][nt][2], acc[mt][nt][3]);
                float2 c0f = __half22float2(c0h);
                float2 c1f = __half22float2(c1h);
                __half2 xc0 = __floats2half2_rn(x0.x * c0f.x, x0.y * c0f.y);
                __half2 xc1 = __floats2half2_rn(x1.x * c1f.x, x1.y * c1f.y);
                *(__half2*)(g_c2qH + base0 + gcol) = c0h;
                *(__half2*)(g_c2qH + base0 + 8 * 1024 + gcol) = c1h;
                *(__half2*)(g_xcH + base0 + gcol) = xc0;
                *(__half2*)(g_xcH + base0 + 8 * 1024 + gcol) = xc1;
            }
        } else {
            int mk0 = mask_at(mask, grow0, isb);
            int mk1 = mask_at(mask, grow0 + 8, isb);
            float* o0 = out + (size_t)grow0 * 1024;
            #pragma unroll
            for (int nt = 0; nt < 4; nt++) {
                int gcol = n0 + wn * 32 + nt * 8 + 2 * t;
                float2 b2 = *(const float2*)(bias + gcol);
                float2 r0, r1;
                r0.x = mk0 ? 0.f : fmaxf(acc[mt][nt][0] + b2.x, 0.f);
                r0.y = mk0 ? 0.f : fmaxf(acc[mt][nt][1] + b2.y, 0.f);
                r1.x = mk1 ? 0.f : fmaxf(acc[mt][nt][2] + b2.x, 0.f);
                r1.y = mk1 ? 0.f : fmaxf(acc[mt][nt][3] + b2.y, 0.f);
                *(float2*)(o0 + gcol) = r0;
                *(float2*)(o0 + 8 * 1024 + gcol) = r1;
            }
        }
    }
}

// ======================= launch =============================================
extern "C" void kernel_launch(void* const* d_in, const int* in_sizes, int n_in,
                              void* d_out, int out_size) {
    const float* inp  = (const float*)d_in[0];
    const void*  mask = d_in[1];
    const float* wsim = (const float*)d_in[2];
    const float* Wm   = (const float*)d_in[3];
    const float* bias = (const float*)d_in[4];
    float* out = (float*)d_out;

    static bool attr_done = false;
    if (!attr_done) {
        cudaFuncSetAttribute(k_gemm_mma<1>, cudaFuncAttributeMaxDynamicSharedMemorySize, SMEM_TOTAL);
        cudaFuncSetAttribute(k_gemm_mma<2>, cudaFuncAttributeMaxDynamicSharedMemorySize, SMEM_TOTAL);
        cudaFuncSetAttribute(k_gemm_mma<3>, cudaFuncAttributeMaxDynamicSharedMemorySize, SMEM_TOTAL);
        attr_done = true;
    }

    k_detect<<<1, 256>>>((const unsigned char*)mask);
    k_prep_all<<<dim3(32, 32, 16), dim3(32, 8)>>>(inp, wsim);
    k_sq<<<(B_ * L_) / 8, 256>>>(inp, wsim);
    k_transpose_wm<<<dim3(32, 96), dim3(32, 8)>>>(Wm);

    k_gemm_mma<1><<<dim3(8, 8, 16), 256, SMEM_TOTAL>>>(bias, mask, out);
    k_softmax<<<B_ * L_, 256>>>(mask);
    k_gemm_mma<2><<<dim3(8, 8, 16), 256, SMEM_TOTAL>>>(bias, mask, out);
    k_gemm_mma<3><<<dim3(8, 128, 1), 256, SMEM_TOTAL>>>(bias, mask, out);
}

// round 17
// speedup vs baseline: 1.0123x; 1.0123x over previous
#include <cuda_runtime.h>
#include <cuda_fp16.h>
#include <cstdint>
#include <math.h>

// Problem dims (fixed per reference)
constexpr int B_ = 16;
constexpr int L_ = 1024;
constexpr int D_ = 1024;
#define NEGV (-1e10f)

// ======================= static device scratch ==============================
__device__ __align__(16) float  g_scores[(size_t)B_ * L_ * L_]; // fp32 scores
__device__ __align__(16) __half g_attnH[(size_t)B_ * L_ * L_];  // half attn
__device__ __align__(16) __half g_awH[(size_t)B_ * L_ * D_];    // half(inp*w3)
__device__ __align__(16) __half g_inpH[(size_t)B_ * L_ * D_];   // half(inp)
__device__ __align__(16) __half g_inpTH[(size_t)B_ * L_ * D_];  // half(inp)^T per batch
__device__ __align__(16) __half g_c2qH[(size_t)B_ * L_ * D_];   // half(c2q)
__device__ __align__(16) __half g_xcH[(size_t)B_ * L_ * D_];    // half(inp*c2q)
__device__ __align__(16) __half g_WmTH[(size_t)3 * D_ * D_];    // half(Wm)^T [D, 3D]
__device__ __align__(16) float  g_sq[B_ * L_];
__device__ int g_mask_is_byte;

// ======================= small helpers ======================================
__device__ __forceinline__ uint32_t smem_u32(const void* p) {
    uint32_t a;
    asm("{ .reg .u64 t; cvta.to.shared.u64 t, %1; cvt.u32.u64 %0, t; }" : "=r"(a) : "l"(p));
    return a;
}
__device__ __forceinline__ void cp16(uint32_t dst, const void* src) {
    asm volatile("cp.async.cg.shared.global [%0], [%1], 16;" :: "r"(dst), "l"(src));
}
__device__ __forceinline__ int mask_at(const void* mask, int idx, int is_byte) {
    if (is_byte) return ((const unsigned char*)mask)[idx] != 0;
    return ((const int*)mask)[idx] != 0;
}
__device__ __forceinline__ void mma_f16(float* d, const uint32_t* a, const uint32_t* b) {
    asm volatile(
        "mma.sync.aligned.m16n8k16.row.col.f32.f16.f16.f32 "
        "{%0,%1,%2,%3}, {%4,%5,%6,%7}, {%8,%9}, {%0,%1,%2,%3};"
        : "+f"(d[0]), "+f"(d[1]), "+f"(d[2]), "+f"(d[3])
        : "r"(a[0]), "r"(a[1]), "r"(a[2]), "r"(a[3]), "r"(b[0]), "r"(b[1]));
}
__device__ __forceinline__ void ldsm_x4(uint32_t addr, uint32_t& r0, uint32_t& r1,
                                        uint32_t& r2, uint32_t& r3) {
    asm volatile("ldmatrix.sync.aligned.m8n8.x4.shared.b16 {%0,%1,%2,%3}, [%4];"
                 : "=r"(r0), "=r"(r1), "=r"(r2), "=r"(r3) : "r"(addr));
}

// ======================= mask dtype autodetect ==============================
__global__ void k_detect(const unsigned char* __restrict__ mask) {
    __shared__ int found;
    if (threadIdx.x == 0) found = 0;
    __syncthreads();
    int any = 0;
    for (int p = threadIdx.x; p < B_ * L_; p += blockDim.x)
        if ((p & 3) && mask[p]) any = 1;
    if (any) atomicOr(&found, 1);
    __syncthreads();
    if (threadIdx.x == 0) g_mask_is_byte = found;
}

// ======================= fused prep: awH, inpH, inpTH (one read of inp) =====
__global__ void k_prep_all(const float* __restrict__ inp, const float* __restrict__ wsim) {
    __shared__ float t[32][33];
    int b  = blockIdx.z;
    int d0 = blockIdx.x * 32;
    int j0 = blockIdx.y * 32;
    const float* src = inp + (size_t)b * L_ * D_;
    float w3v = wsim[2 * D_ + d0 + threadIdx.x];
    #pragma unroll
    for (int k = 0; k < 4; k++) {
        int j = j0 + threadIdx.y + 8 * k;
        float v = src[(size_t)j * D_ + d0 + threadIdx.x];
        t[threadIdx.y + 8 * k][threadIdx.x] = v;
        size_t off = (size_t)b * L_ * D_ + (size_t)j * D_ + d0 + threadIdx.x;
        g_inpH[off] = __float2half_rn(v);
        g_awH[off]  = __float2half_rn(v * w3v);
    }
    __syncthreads();
    __half* dst = g_inpTH + (size_t)b * L_ * D_;
    #pragma unroll
    for (int k = 0; k < 4; k++)
        dst[(size_t)(d0 + threadIdx.y + 8 * k) * L_ + j0 + threadIdx.x] =
            __float2half_rn(t[threadIdx.x][threadIdx.y + 8 * k]);
}

// ======================= s_q (fp32) =========================================
// s_c (per-row constant) cancels under softmax and is dropped entirely.
__global__ void k_sq(const float* __restrict__ inp, const float* __restrict__ wsim) {
    int row = blockIdx.x * (blockDim.x >> 5) + (threadIdx.x >> 5);
    if (row >= B_ * L_) return;
    int lane = threadIdx.x & 31;
    const float* x = inp + (size_t)row * D_;
    float s2 = 0.f;
    for (int d = lane; d < D_; d += 32)
        s2 += x[d] * wsim[D_ + d];
    #pragma unroll
    for (int o = 16; o; o >>= 1)
        s2 += __shfl_xor_sync(0xffffffffu, s2, o);
    if (lane == 0) g_sq[row] = s2;
}

// ======================= transpose Wm (write half) ==========================
__global__ void k_transpose_wm(const float* __restrict__ Wm) {
    __shared__ float t[32][33];
    int n0 = blockIdx.x * 32;   // col of Wm (D)
    int k0 = blockIdx.y * 32;   // row of Wm (3D)
    #pragma unroll
    for (int k = 0; k < 4; k++)
        t[threadIdx.y + 8 * k][threadIdx.x] =
            Wm[(size_t)(k0 + threadIdx.y + 8 * k) * D_ + n0 + threadIdx.x];
    __syncthreads();
    #pragma unroll
    for (int k = 0; k < 4; k++)
        g_WmTH[(size_t)(n0 + threadIdx.y + 8 * k) * (3 * D_) + k0 + threadIdx.x] =
            __float2half_rn(t[threadIdx.x][threadIdx.y + 8 * k]);
}

// ======================= softmax: fp32 scores -> half attn ==================
__global__ void k_softmax(const void* __restrict__ mask) {
    __shared__ float redmax[8];
    __shared__ float redsum[8];
    int row = blockIdx.x;
    int b   = row >> 10;
    int isb = g_mask_is_byte;
    const float* s = g_scores + (size_t)row * L_;
    __half* a = g_attnH + (size_t)row * L_;
    int t = threadIdx.x;

    float4 v = ((const float4*)s)[t];
    int j0 = t << 2;
    int base = b * L_;
    if (mask_at(mask, base + j0 + 0, isb)) v.x = NEGV;
    if (mask_at(mask, base + j0 + 1, isb)) v.y = NEGV;
    if (mask_at(mask, base + j0 + 2, isb)) v.z = NEGV;
    if (mask_at(mask, base + j0 + 3, isb)) v.w = NEGV;

    float mx = fmaxf(fmaxf(v.x, v.y), fmaxf(v.z, v.w));
    #pragma unroll
    for (int o = 16; o; o >>= 1) mx = fmaxf(mx, __shfl_xor_sync(0xffffffffu, mx, o));
    if ((t & 31) == 0) redmax[t >> 5] = mx;
    __syncthreads();
    mx = fmaxf(fmaxf(fmaxf(redmax[0], redmax[1]), fmaxf(redmax[2], redmax[3])),
               fmaxf(fmaxf(redmax[4], redmax[5]), fmaxf(redmax[6], redmax[7])));

    v.x = __expf(v.x - mx); v.y = __expf(v.y - mx);
    v.z = __expf(v.z - mx); v.w = __expf(v.w - mx);
    float sm = v.x + v.y + v.z + v.w;
    #pragma unroll
    for (int o = 16; o; o >>= 1) sm += __shfl_xor_sync(0xffffffffu, sm, o);
    if ((t & 31) == 0) redsum[t >> 5] = sm;
    __syncthreads();
    sm = redsum[0] + redsum[1] + redsum[2] + redsum[3] +
         redsum[4] + redsum[5] + redsum[6] + redsum[7];
    float inv = 1.0f / sm;
    ((__half2*)a)[2 * t]     = __floats2half2_rn(v.x * inv, v.y * inv);
    ((__half2*)a)[2 * t + 1] = __floats2half2_rn(v.z * inv, v.w * inv);
}

// ======================= fp16 HMMA GEMM (ldmatrix, BK=64) ===================
// CTA tile M=128, N=128, BK=64 halves. 8 warps (2 M x 4 N), each 64x32 via
// m16n8k16. SMEM rows 128B data padded to 144B stride — conflict-free for
// ldmatrix (banks 4r mod 32). 3-stage cp.async pipeline, occupancy 2.
// Next chunk's cp.async is issued right after the barrier (before fragment
// loads) so LDGSTS gets the full MMA block as latency cover. Fragments are
// single-buffered (R12's double-buffering spilled registers and regressed).
// E=1: scores(fp32) = awH @ inpH^T (+sq)        [per batch]
// E=2: c2qH/xcH     = attnH @ inpTH^T           [per batch]
// E=3: out(fp32)    = [inpH|c2qH|xcH] @ WmTH^T (+bias, relu, mask)
constexpr int ROWB = 144;                        // smem row stride (bytes)
constexpr int STAGE_BYTES = 2 * 128 * ROWB;      // 36864
constexpr int SMEM_TOTAL = 3 * STAGE_BYTES;      // 110592

template <int E>
__global__ __launch_bounds__(256, 2)
void k_gemm_mma(const float* __restrict__ bias, const void* __restrict__ mask,
                float* __restrict__ out) {
    extern __shared__ char smem[];
    uint32_t sbase = smem_u32(smem);
    int tid = threadIdx.x;
    int lane = tid & 31, w = tid >> 5;
    int g = lane >> 2, t = lane & 3;
    int wm = w & 1, wn = w >> 1;                 // warp grid 2 (M) x 4 (N)

    constexpr int NCH = (E == 3) ? 48 : 16;      // K chunks of 64 halves
    constexpr int LDB = (E == 3) ? 3072 : 1024;

    int b  = blockIdx.z;
    int i0 = blockIdx.y * 128;
    int n0 = blockIdx.x * 128;

    const __half *A0, *A1 = nullptr, *A2 = nullptr, *Bb;
    if (E == 1) {
        A0 = g_awH  + ((size_t)b << 20) + (size_t)i0 * 1024;
        Bb = g_inpH + ((size_t)b << 20) + (size_t)n0 * 1024;
    } else if (E == 2) {
        A0 = g_attnH + ((size_t)b << 20) + (size_t)i0 * 1024;
        Bb = g_inpTH + ((size_t)b << 20) + (size_t)n0 * 1024;
    } else {
        A0 = g_inpH + (size_t)i0 * 1024;
        A1 = g_c2qH + (size_t)i0 * 1024;
        A2 = g_xcH  + (size_t)i0 * 1024;
        Bb = g_WmTH + (size_t)n0 * 3072;
    }

    // ldmatrix per-lane address offsets (within a stage)
    int mat = lane >> 3, mrow = lane & 7;
    // A (x4: {rows+0,+0B},{rows+8,+0B},{rows+0,+16B},{rows+8,+16B})
    uint32_t offA = (uint32_t)(wm * 64 + (mat & 1) * 8 + mrow) * ROWB + (mat >> 1) * 16;
    // B (x4: {nt0,+0B},{nt0,+16B},{nt1,+0B},{nt1,+16B})
    uint32_t offB = (uint32_t)(wn * 32 + (mat >> 1) * 8 + mrow) * ROWB + (mat & 1) * 16;

    // load one K-chunk (64 halves = 128B/row): A 128 rows, B 128 rows
    auto loadc = [&](int kc, int s) {
        const __half* Ab;
        int koff;
        if (E == 3) {
            int seg = kc >> 4;
            koff = (kc & 15) * 64;
            Ab = (seg == 0) ? A0 : (seg == 1) ? A1 : A2;
        } else {
            Ab = A0; koff = kc * 64;
        }
        const __half* Bv = Bb + (size_t)kc * 64;
        uint32_t sa = sbase + s * STAGE_BYTES;
        uint32_t sb = sa + 128 * ROWB;
        #pragma unroll
        for (int r = 0; r < 4; r++) {
            int id = tid + r * 256;
            int row = id >> 3, c8 = id & 7;
            cp16(sa + row * ROWB + c8 * 16, Ab + (size_t)row * 1024 + koff + c8 * 8);
        }
        #pragma unroll
        for (int r = 0; r < 4; r++) {
            int id = tid + r * 256;
            int row = id >> 3, c8 = id & 7;
            cp16(sb + row * ROWB + c8 * 16, Bv + (size_t)row * LDB + c8 * 8);
        }
    };

    float acc[4][4][4];
    #pragma unroll
    for (int i = 0; i < 4; i++)
        #pragma unroll
        for (int j = 0; j < 4; j++)
            #pragma unroll
            for (int q = 0; q < 4; q++) acc[i][j][q] = 0.f;

    // prologue: stages 0..1
    #pragma unroll
    for (int c = 0; c < 2; c++) {
        loadc(c, c);
        asm volatile("cp.async.commit_group;" ::: "memory");
    }

    int stage = 0;
    for (int kc = 0; kc < NCH; kc++) {
        asm volatile("cp.async.wait_group 1;" ::: "memory");
        __syncthreads();

        // issue next chunk's global->smem copies FIRST (stage ls was last
        // read in iteration kc-1; the barrier above makes overwrite safe) —
        // gives the LDGSTS the whole MMA block below as latency cover.
        int lc = kc + 2;
        if (lc < NCH) {
            int ls = stage + 2; if (ls >= 3) ls -= 3;
            loadc(lc, ls);
        }
        asm volatile("cp.async.commit_group;" ::: "memory");

        uint32_t As = sbase + stage * STAGE_BYTES;
        uint32_t Bs = As + 128 * ROWB;
        #pragma unroll
        for (int ks = 0; ks < 4; ks++) {
            uint32_t kbyte = ks * 32;               // 16 halves * 2B
            uint32_t af[4][4], bf[4][2];
            #pragma unroll
            for (int mt = 0; mt < 4; mt++)
                ldsm_x4(As + offA + mt * 16 * ROWB + kbyte,
                        af[mt][0], af[mt][1], af[mt][2], af[mt][3]);
            #pragma unroll
            for (int np = 0; np < 2; np++)
                ldsm_x4(Bs + offB + np * 16 * ROWB + kbyte,
                        bf[2 * np][0], bf[2 * np][1],
                        bf[2 * np + 1][0], bf[2 * np + 1][1]);
            #pragma unroll
            for (int mt = 0; mt < 4; mt++)
                #pragma unroll
                for (int nt = 0; nt < 4; nt++)
                    mma_f16(acc[mt][nt], af[mt], bf[nt]);
        }

        if (++stage == 3) stage = 0;
    }

    // ---------------- epilogue ------------------------------------------------
    int isb = (E == 3) ? g_mask_is_byte : 0;
    #pragma unroll
    for (int mt = 0; mt < 4; mt++) {
        int grow0 = i0 + wm * 64 + mt * 16 + g;      // rows grow0, grow0+8
        if (E == 1) {
            float* c0 = g_scores + ((size_t)b << 20) + (size_t)grow0 * 1024;
            #pragma unroll
            for (int nt = 0; nt < 4; nt++) {
                int gcol = n0 + wn * 32 + nt * 8 + 2 * t;
                float2 sq2 = *(const float2*)(g_sq + b * 1024 + gcol);
                float2 o0 = make_float2(acc[mt][nt][0] + sq2.x,
                                        acc[mt][nt][1] + sq2.y);
                float2 o1 = make_float2(acc[mt][nt][2] + sq2.x,
                                        acc[mt][nt][3] + sq2.y);
                *(float2*)(c0 + gcol) = o0;
                *(float2*)(c0 + 8 * 1024 + gcol) = o1;
            }
        } else if (E == 2) {
            size_t base0 = ((size_t)(b * 1024 + grow0)) * 1024;
            #pragma unroll
            for (int nt = 0; nt < 4; nt++) {
                int gcol = n0 + wn * 32 + nt * 8 + 2 * t;
                float2 x0 = __half22float2(*(const __half2*)(g_inpH + base0 + gcol));
                float2 x1 = __half22float2(*(const __half2*)(g_inpH + base0 + 8 * 1024 + gcol));
                __half2 c0h = __floats2half2_rn(acc[mt][nt][0], acc[mt][nt][1]);
                __half2 c1h = __floats2half2_rn(acc[mt][nt][2], acc[mt][nt][3]);
                float2 c0f = __half22float2(c0h);
                float2 c1f = __half22float2(c1h);
                __half2 xc0 = __floats2half2_rn(x0.x * c0f.x, x0.y * c0f.y);
                __half2 xc1 = __floats2half2_rn(x1.x * c1f.x, x1.y * c1f.y);
                *(__half2*)(g_c2qH + base0 + gcol) = c0h;
                *(__half2*)(g_c2qH + base0 + 8 * 1024 + gcol) = c1h;
                *(__half2*)(g_xcH + base0 + gcol) = xc0;
                *(__half2*)(g_xcH + base0 + 8 * 1024 + gcol) = xc1;
            }
        } else {
            int mk0 = mask_at(mask, grow0, isb);
            int mk1 = mask_at(mask, grow0 + 8, isb);
            float* o0 = out + (size_t)grow0 * 1024;
            #pragma unroll
            for (int nt = 0; nt < 4; nt++) {
                int gcol = n0 + wn * 32 + nt * 8 + 2 * t;
                float2 b2 = *(const float2*)(bias + gcol);
                float2 r0, r1;
                r0.x = mk0 ? 0.f : fmaxf(acc[mt][nt][0] + b2.x, 0.f);
                r0.y = mk0 ? 0.f : fmaxf(acc[mt][nt][1] + b2.y, 0.f);
                r1.x = mk1 ? 0.f : fmaxf(acc[mt][nt][2] + b2.x, 0.f);
                r1.y = mk1 ? 0.f : fmaxf(acc[mt][nt][3] + b2.y, 0.f);
                *(float2*)(o0 + gcol) = r0;
                *(float2*)(o0 + 8 * 1024 + gcol) = r1;
            }
        }
    }
}

// ======================= launch =============================================
extern "C" void kernel_launch(void* const* d_in, const int* in_sizes, int n_in,
                              void* d_out, int out_size) {
    const float* inp  = (const float*)d_in[0];
    const void*  mask = d_in[1];
    const float* wsim = (const float*)d_in[2];
    const float* Wm   = (const float*)d_in[3];
    const float* bias = (const float*)d_in[4];
    float* out = (float*)d_out;

    static bool attr_done = false;
    if (!attr_done) {
        cudaFuncSetAttribute(k_gemm_mma<1>, cudaFuncAttributeMaxDynamicSharedMemorySize, SMEM_TOTAL);
        cudaFuncSetAttribute(k_gemm_mma<2>, cudaFuncAttributeMaxDynamicSharedMemorySize, SMEM_TOTAL);
        cudaFuncSetAttribute(k_gemm_mma<3>, cudaFuncAttributeMaxDynamicSharedMemorySize, SMEM_TOTAL);
        attr_done = true;
    }

    k_detect<<<1, 256>>>((const unsigned char*)mask);
    k_prep_all<<<dim3(32, 32, 16), dim3(32, 8)>>>(inp, wsim);
    k_sq<<<(B_ * L_) / 8, 256>>>(inp, wsim);
    k_transpose_wm<<<dim3(32, 96), dim3(32, 8)>>>(Wm);

    k_gemm_mma<1><<<dim3(8, 8, 16), 256, SMEM_TOTAL>>>(bias, mask, out);
    k_softmax<<<B_ * L_, 256>>>(mask);
    k_gemm_mma<2><<<dim3(8, 8, 16), 256, SMEM_TOTAL>>>(bias, mask, out);
    k_gemm_mma<3><<<dim3(8, 128, 1), 256, SMEM_TOTAL>>>(bias, mask, out);
}